// round 8
// baseline (speedup 1.0000x reference)
#include <cuda_runtime.h>
#include <cuda_bf16.h>
#include <cstdint>

// ---------------- problem constants ----------------
constexpr int NB = 8, NT = 2048, ND = 1024, NF = 4096, NE = 8, NP = 16;
constexpr int BM = 128, BN = 128, BK = 16;
constexpr int THREADS = 256;

// smem layout (bytes): A row = 16*2+16 = 48B (conflict-free), B row = 272B
constexpr int A_STRIDE_B = 48;
constexpr int B_STRIDE_B = 272;
constexpr int A_TILE = BM * A_STRIDE_B;            // 6144
constexpr int B_TILE = BK * B_STRIDE_B;            // 4352
constexpr int BOFF   = 2 * A_TILE;                 // 12288
constexpr int BUF    = 2 * A_TILE + 2 * B_TILE;    // 20992
constexpr int NSTAGE = 5;
constexpr int SMEM_TOTAL = NSTAGE * BUF;           // 104960 (x2 CTAs = 209920 < 228KB)

// ---------------- device scratch (allocation-free) ----------------
__device__ float g_ppart[NB * ND * 16];
__device__ int   g_eidx[NP];
__device__ float g_wgt[NP];
__device__ __nv_bfloat16 g_xh[(size_t)NB*NT*ND],  g_xl[(size_t)NB*NT*ND];
__device__ __nv_bfloat16 g_w1h[(size_t)NE*ND*NF], g_w1l[(size_t)NE*ND*NF];
__device__ __nv_bfloat16 g_w2h[(size_t)NE*NF*ND], g_w2l[(size_t)NE*NF*ND];
__device__ __nv_bfloat16 g_hh[(size_t)NP*NT*NF],  g_hl[(size_t)NP*NT*NF];

// ---------------- PTX helpers ----------------
__device__ __forceinline__ uint32_t s2u(const void* p) {
    uint32_t a;
    asm("{ .reg .u64 t; cvta.to.shared.u64 t, %1; cvt.u32.u64 %0, t; }" : "=r"(a) : "l"(p));
    return a;
}
__device__ __forceinline__ void cp16(uint32_t dst, const void* src) {
    asm volatile("cp.async.cg.shared.global [%0], [%1], 16;" :: "r"(dst), "l"(src));
}
#define CP_COMMIT() asm volatile("cp.async.commit_group;" ::: "memory")
#define CP_WAIT(n)  asm volatile("cp.async.wait_group %0;" :: "n"(n) : "memory")

__device__ __forceinline__ void ldm4(uint32_t* r, uint32_t a) {
    asm volatile("ldmatrix.sync.aligned.m8n8.x4.shared.b16 {%0,%1,%2,%3}, [%4];"
        : "=r"(r[0]), "=r"(r[1]), "=r"(r[2]), "=r"(r[3]) : "r"(a));
}
__device__ __forceinline__ void ldm4t(uint32_t* r, uint32_t a) {
    asm volatile("ldmatrix.sync.aligned.m8n8.x4.trans.shared.b16 {%0,%1,%2,%3}, [%4];"
        : "=r"(r[0]), "=r"(r[1]), "=r"(r[2]), "=r"(r[3]) : "r"(a));
}
__device__ __forceinline__ void mma(float* d, const uint32_t* a, uint32_t b0, uint32_t b1) {
    asm volatile("mma.sync.aligned.m16n8k16.row.col.f32.bf16.bf16.f32 "
        "{%0,%1,%2,%3}, {%4,%5,%6,%7}, {%8,%9}, {%0,%1,%2,%3};"
        : "+f"(d[0]), "+f"(d[1]), "+f"(d[2]), "+f"(d[3])
        : "r"(a[0]), "r"(a[1]), "r"(a[2]), "r"(a[3]), "r"(b0), "r"(b1));
}
__device__ __forceinline__ uint32_t pack_bf2(float a, float b) {
    __nv_bfloat162 t(__float2bfloat16(a), __float2bfloat16(b));
    return *(uint32_t*)&t;
}

// ---------------- prepass kernels ----------------
__global__ void k_pool(const float* __restrict__ x) {
    int b = blockIdx.y, ch = blockIdx.z;
    int d = blockIdx.x * 256 + threadIdx.x;
    const float* xp = x + ((size_t)b * NT + ch * 128) * ND + d;
    float s = 0.f;
#pragma unroll 8
    for (int t = 0; t < 128; ++t) s += xp[(size_t)t * ND];
    g_ppart[(b * ND + d) * 16 + ch] = s;
}

constexpr int N_X4 = NB * NT * ND / 4;
constexpr int N_W4 = NE * ND * NF / 4;
__global__ void k_cvt_all(const float4* __restrict__ x,
                          const float4* __restrict__ W1,
                          const float4* __restrict__ W2) {
    int gid = blockIdx.x * 256 + threadIdx.x;
    const float4* src;  uint32_t *H, *L;  int i;
    if (gid < N_X4) {
        src = x; i = gid;
        H = (uint32_t*)g_xh;  L = (uint32_t*)g_xl;
    } else if (gid < N_X4 + N_W4) {
        src = W1; i = gid - N_X4;
        H = (uint32_t*)g_w1h; L = (uint32_t*)g_w1l;
    } else {
        src = W2; i = gid - N_X4 - N_W4;
        H = (uint32_t*)g_w2h; L = (uint32_t*)g_w2l;
    }
    float4 v = src[i];
    float h0 = __bfloat162float(__float2bfloat16(v.x));
    float h1 = __bfloat162float(__float2bfloat16(v.y));
    float h2 = __bfloat162float(__float2bfloat16(v.z));
    float h3 = __bfloat162float(__float2bfloat16(v.w));
    H[2*i]   = pack_bf2(v.x, v.y);
    H[2*i+1] = pack_bf2(v.z, v.w);
    L[2*i]   = pack_bf2(v.x - h0, v.y - h1);
    L[2*i+1] = pack_bf2(v.z - h2, v.w - h3);
}

__global__ void k_route(const float* __restrict__ Wr) {
    __shared__ float pooled[NB * ND];
    __shared__ float lg[NB][NE];
    int t = threadIdx.x;   // 64 threads
    for (int i = t; i < NB * ND; i += 64) {
        float s = 0.f;
#pragma unroll
        for (int ch = 0; ch < 16; ++ch) s += g_ppart[i * 16 + ch];
        pooled[i] = s * (1.0f / NT);
    }
    __syncthreads();
    if (t < NB * NE) {
        int b = t / NE, e = t % NE;
        float s = 0.f;
        for (int d = 0; d < ND; ++d) s += pooled[b * ND + d] * Wr[d * NE + e];
        lg[b][e] = s;
    }
    __syncthreads();
    if (t < NB) {
        int b = t;
        int i0 = 0; float v0 = lg[b][0];
#pragma unroll
        for (int e = 1; e < NE; ++e) if (lg[b][e] > v0) { v0 = lg[b][e]; i0 = e; }
        int i1 = (i0 == 0) ? 1 : 0; float v1 = lg[b][i1];
#pragma unroll
        for (int e = 0; e < NE; ++e) if (e != i0 && lg[b][e] > v1) { v1 = lg[b][e]; i1 = e; }
        float e1 = expf(v1 - v0);
        float inv = 1.f / (1.f + e1);
        g_eidx[2 * b] = i0;  g_eidx[2 * b + 1] = i1;
        g_wgt[2 * b] = inv;  g_wgt[2 * b + 1] = e1 * inv;
    }
}

// ---------------- GEMM mainloop pieces ----------------
// Stage: A [128 x 16] hi+lo, B [16 x 128] hi+lo; 4 cp.async per thread.
__device__ __forceinline__ void load_stage(uint32_t smb, int buf, int tid,
    const __nv_bfloat16* __restrict__ Ah, const __nv_bfloat16* __restrict__ Al, int lda,
    const __nv_bfloat16* __restrict__ Bh, const __nv_bfloat16* __restrict__ Bl, int ldb, int k0)
{
    uint32_t base = smb + buf * BUF;
    {   // A: 256 16B chunks per tile
        int row = tid >> 1, kc = tid & 1;
        size_t go = (size_t)row * lda + k0 + kc * 8;
        uint32_t d = base + row * A_STRIDE_B + kc * 16;
        cp16(d, Ah + go);
        cp16(d + A_TILE, Al + go);
    }
    {   // B: 256 16B chunks per tile
        int row = tid >> 4, nc = tid & 15;
        size_t go = (size_t)(k0 + row) * ldb + nc * 8;
        uint32_t d = base + BOFF + row * B_STRIDE_B + nc * 16;
        cp16(d, Bh + go);
        cp16(d + B_TILE, Bl + go);
    }
}

// Warp tile 64M x 32N, one K16 per stage. A double-buffered across mt;
// per-mt mma emitted pass-separated (dependency distance 4 per accumulator).
__device__ __forceinline__ void compute_stage(uint32_t smb, int buf, int lane,
                                              int warpM, int warpN, float acc[4][4][4])
{
    uint32_t base = smb + buf * BUF;
    int lr = lane & 15, lc = lane >> 4;

    uint32_t bh[2][4], bl[2][4];
#pragma unroll
    for (int nt = 0; nt < 2; ++nt) {
        uint32_t bd = base + BOFF + lr * B_STRIDE_B + (warpN * 32 + nt * 16 + lc * 8) * 2;
        ldm4t(bh[nt], bd);
        ldm4t(bl[nt], bd + B_TILE);
    }

    uint32_t ah[2][4], al[2][4];
    {
        uint32_t ad = base + (warpM * 64 + lr) * A_STRIDE_B + lc * 16;
        ldm4(ah[0], ad);
        ldm4(al[0], ad + A_TILE);
    }
#pragma unroll
    for (int mt = 0; mt < 4; ++mt) {
        if (mt < 3) {   // prefetch A(mt+1)
            uint32_t ad = base + (warpM * 64 + (mt + 1) * 16 + lr) * A_STRIDE_B + lc * 16;
            ldm4(ah[(mt + 1) & 1], ad);
            ldm4(al[(mt + 1) & 1], ad + A_TILE);
        }
        const uint32_t* A_h = ah[mt & 1];
        const uint32_t* A_l = al[mt & 1];
        // pass 1: hi*hi over all 4 accumulators
#pragma unroll
        for (int nt = 0; nt < 2; ++nt)
#pragma unroll
            for (int n8 = 0; n8 < 2; ++n8)
                mma(acc[mt][nt * 2 + n8], A_h, bh[nt][2 * n8], bh[nt][2 * n8 + 1]);
        // pass 2: hi*lo
#pragma unroll
        for (int nt = 0; nt < 2; ++nt)
#pragma unroll
            for (int n8 = 0; n8 < 2; ++n8)
                mma(acc[mt][nt * 2 + n8], A_h, bl[nt][2 * n8], bl[nt][2 * n8 + 1]);
        // pass 3: lo*hi
#pragma unroll
        for (int nt = 0; nt < 2; ++nt)
#pragma unroll
            for (int n8 = 0; n8 < 2; ++n8)
                mma(acc[mt][nt * 2 + n8], A_l, bh[nt][2 * n8], bh[nt][2 * n8 + 1]);
    }
}

// ---------------- GEMM1: h[p] = w * gelu(x[b] @ W1[e] + b1[e]) --------------
__global__ __launch_bounds__(THREADS, 2)
void k_mm1(const float* __restrict__ b1) {
    extern __shared__ char sm[];
    const uint32_t smb = s2u(sm);
    const int tid = threadIdx.x, lane = tid & 31, w = tid >> 5;
    const int warpM = w >> 2, warpN = w & 3;
    const int p = blockIdx.z, b = p >> 1;
    const int e = g_eidx[p];
    const float wsc = g_wgt[p];
    const int m0 = blockIdx.y * BM, n0 = blockIdx.x * BN;

    const __nv_bfloat16* Ah = g_xh  + ((size_t)b * NT + m0) * ND;
    const __nv_bfloat16* Al = g_xl  + ((size_t)b * NT + m0) * ND;
    const __nv_bfloat16* Bh = g_w1h + (size_t)e * ND * NF + n0;
    const __nv_bfloat16* Bl = g_w1l + (size_t)e * ND * NF + n0;

    float acc[4][4][4];
#pragma unroll
    for (int i = 0; i < 4; ++i)
#pragma unroll
        for (int j = 0; j < 4; ++j)
#pragma unroll
            for (int q = 0; q < 4; ++q) acc[i][j][q] = 0.f;

    constexpr int KT = ND / BK;   // 64
#pragma unroll
    for (int s = 0; s < NSTAGE - 1; ++s) {   // prologue: 4 stages in flight
        load_stage(smb, s, tid, Ah, Al, ND, Bh, Bl, NF, s * BK);
        CP_COMMIT();
    }
    int buf = 0, nbuf = NSTAGE - 1;
    for (int s = 0; s < KT; ++s) {
        CP_WAIT(NSTAGE - 2);        // group s landed (<=3 still pending)
        __syncthreads();            // all warps done with compute(s-1)
        if (s + NSTAGE - 1 < KT) {
            load_stage(smb, nbuf, tid, Ah, Al, ND, Bh, Bl, NF, (s + NSTAGE - 1) * BK);
            CP_COMMIT();
        }
        compute_stage(smb, buf, lane, warpM, warpN, acc);
        buf = (buf == NSTAGE - 1) ? 0 : buf + 1;
        nbuf = (nbuf == NSTAGE - 1) ? 0 : nbuf + 1;
    }

    // epilogue: bias + exact erf-gelu + router weight, split to bf16 hi/lo
    const float* bg = b1 + (size_t)e * NF;
#pragma unroll
    for (int mt = 0; mt < 4; ++mt)
#pragma unroll
        for (int nn = 0; nn < 4; ++nn) {
            int row = m0 + warpM * 64 + mt * 16 + (lane >> 2);
            int col = n0 + warpN * 32 + nn * 8 + (lane & 3) * 2;
            float bv0 = bg[col], bv1 = bg[col + 1];
            float v00 = acc[mt][nn][0] + bv0, v01 = acc[mt][nn][1] + bv1;
            float v10 = acc[mt][nn][2] + bv0, v11 = acc[mt][nn][3] + bv1;
            float g00 = wsc * v00 * normcdff(v00);
            float g01 = wsc * v01 * normcdff(v01);
            float g10 = wsc * v10 * normcdff(v10);
            float g11 = wsc * v11 * normcdff(v11);
            size_t o0 = ((size_t)p * NT + row) * NF + col;
            size_t o1 = ((size_t)p * NT + row + 8) * NF + col;
            float h00 = __bfloat162float(__float2bfloat16(g00));
            float h01 = __bfloat162float(__float2bfloat16(g01));
            float h10 = __bfloat162float(__float2bfloat16(g10));
            float h11 = __bfloat162float(__float2bfloat16(g11));
            *(uint32_t*)&g_hh[o0] = pack_bf2(g00, g01);
            *(uint32_t*)&g_hh[o1] = pack_bf2(g10, g11);
            *(uint32_t*)&g_hl[o0] = pack_bf2(g00 - h00, g01 - h01);
            *(uint32_t*)&g_hl[o1] = pack_bf2(g10 - h10, g11 - h11);
        }
}

// ---------------- GEMM2: out[b] = sum_k h[b,k] @ W2[e_k] + weighted bias ----
__global__ __launch_bounds__(THREADS, 2)
void k_mm2(const float* __restrict__ b2, float* __restrict__ out) {
    extern __shared__ char sm[];
    const uint32_t smb = s2u(sm);
    const int tid = threadIdx.x, lane = tid & 31, w = tid >> 5;
    const int warpM = w >> 2, warpN = w & 3;
    const int b = blockIdx.z;
    const int e0 = g_eidx[2 * b], e1 = g_eidx[2 * b + 1];
    const float w0 = g_wgt[2 * b], w1 = g_wgt[2 * b + 1];
    const int m0 = blockIdx.y * BM, n0 = blockIdx.x * BN;

    float acc[4][4][4];
#pragma unroll
    for (int i = 0; i < 4; ++i)
#pragma unroll
        for (int j = 0; j < 4; ++j)
#pragma unroll
            for (int q = 0; q < 4; ++q) acc[i][j][q] = 0.f;

    constexpr int KSEG = NF / BK;      // 256 stages per expert
    constexpr int KT   = 2 * KSEG;     // 512

    auto stage_ptrs = [&](int s, const __nv_bfloat16*& Ah, const __nv_bfloat16*& Al,
                          const __nv_bfloat16*& Bh, const __nv_bfloat16*& Bl, int& k0) {
        int seg = s >> 8, sl = s & (KSEG - 1);
        int p = 2 * b + seg, e = seg ? e1 : e0;
        Ah = g_hh  + ((size_t)p * NT + m0) * NF;
        Al = g_hl  + ((size_t)p * NT + m0) * NF;
        Bh = g_w2h + (size_t)e * NF * ND + n0;
        Bl = g_w2l + (size_t)e * NF * ND + n0;
        k0 = sl * BK;
    };

#pragma unroll
    for (int s = 0; s < NSTAGE - 1; ++s) {
        const __nv_bfloat16 *Ah, *Al, *Bh, *Bl; int k0;
        stage_ptrs(s, Ah, Al, Bh, Bl, k0);
        load_stage(smb, s, tid, Ah, Al, NF, Bh, Bl, ND, k0);
        CP_COMMIT();
    }
    int buf = 0, nbuf = NSTAGE - 1;
    for (int s = 0; s < KT; ++s) {
        CP_WAIT(NSTAGE - 2);
        __syncthreads();
        if (s + NSTAGE - 1 < KT) {
            const __nv_bfloat16 *Ah, *Al, *Bh, *Bl; int k0;
            stage_ptrs(s + NSTAGE - 1, Ah, Al, Bh, Bl, k0);
            load_stage(smb, nbuf, tid, Ah, Al, NF, Bh, Bl, ND, k0);
            CP_COMMIT();
        }
        compute_stage(smb, buf, lane, warpM, warpN, acc);
        buf = (buf == NSTAGE - 1) ? 0 : buf + 1;
        nbuf = (nbuf == NSTAGE - 1) ? 0 : nbuf + 1;
    }

    // epilogue: weighted bias, final fp32 output
#pragma unroll
    for (int mt = 0; mt < 4; ++mt)
#pragma unroll
        for (int nn = 0; nn < 4; ++nn) {
            int row = m0 + warpM * 64 + mt * 16 + (lane >> 2);
            int col = n0 + warpN * 32 + nn * 8 + (lane & 3) * 2;
            float bv0 = w0 * b2[e0 * ND + col]     + w1 * b2[e1 * ND + col];
            float bv1 = w0 * b2[e0 * ND + col + 1] + w1 * b2[e1 * ND + col + 1];
            float* o0 = out + ((size_t)b * NT + row) * ND + col;
            float* o1 = out + ((size_t)b * NT + row + 8) * ND + col;
            o0[0] = acc[mt][nn][0] + bv0;  o0[1] = acc[mt][nn][1] + bv1;
            o1[0] = acc[mt][nn][2] + bv0;  o1[1] = acc[mt][nn][3] + bv1;
        }
}

// ---------------- launch (k_mm1 at position 4 for ncu) ----------------------
extern "C" void kernel_launch(void* const* d_in, const int* in_sizes, int n_in,
                              void* d_out, int out_size) {
    const float* x  = (const float*)d_in[0];
    const float* Wr = (const float*)d_in[1];
    const float* W1 = (const float*)d_in[2];
    const float* b1 = (const float*)d_in[3];
    const float* W2 = (const float*)d_in[4];
    const float* b2 = (const float*)d_in[5];
    float* out = (float*)d_out;

    cudaFuncSetAttribute(k_mm1, cudaFuncAttributeMaxDynamicSharedMemorySize, SMEM_TOTAL);
    cudaFuncSetAttribute(k_mm2, cudaFuncAttributeMaxDynamicSharedMemorySize, SMEM_TOTAL);

    k_pool<<<dim3(ND / 256, NB, 16), 256>>>(x);                             // 1
    k_route<<<1, 64>>>(Wr);                                                  // 2
    k_cvt_all<<<(N_X4 + 2 * N_W4 + 255) / 256, 256>>>(
        (const float4*)x, (const float4*)W1, (const float4*)W2);             // 3
    k_mm1<<<dim3(NF/BN, NT/BM, NP), THREADS, SMEM_TOTAL>>>(b1);              // 4 <- ncu
    k_mm2<<<dim3(ND/BN, NT/BM, NB), THREADS, SMEM_TOTAL>>>(b2, out);         // 5
}

// round 9
// speedup vs baseline: 1.5147x; 1.5147x over previous
#include <cuda_runtime.h>
#include <cuda_fp16.h>
#include <cstdint>

// ---------------- problem constants ----------------
constexpr int NB = 8, NT = 2048, ND = 1024, NF = 4096, NE = 8, NP = 16;
constexpr int BM = 128, BN = 128, BK = 32;
constexpr int THREADS = 256;

// smem layout (bytes): A row = 32*2+16 = 80B, B row = 128*2+16 = 272B
constexpr int A_STRIDE_B = 80;
constexpr int B_STRIDE_B = 272;
constexpr int A_TILE = BM * A_STRIDE_B;            // 10240 (A single fp16 tile)
constexpr int B_TILE = BK * B_STRIDE_B;            // 8704  (per B tile; hi+lo = 2)
constexpr int BOFF   = A_TILE;                     // 10240
constexpr int BUF    = A_TILE + 2 * B_TILE;        // 27648
constexpr int NSTAGE = 3;
constexpr int SMEM_TOTAL = NSTAGE * BUF;           // 82944 (x2 CTAs = 165888 < 228KB)

// ---------------- device scratch (allocation-free) ----------------
__device__ float g_ppart[NB * ND * 16];
__device__ int   g_eidx[NP];
__device__ float g_wgt[NP];
__device__ __half g_x[(size_t)NB*NT*ND];                                  // A for mm1 (fp16)
__device__ __half g_w1h[(size_t)NE*ND*NF], g_w1l[(size_t)NE*ND*NF];       // W1 hi/lo
__device__ __half g_w2h[(size_t)NE*NF*ND], g_w2l[(size_t)NE*NF*ND];       // W2 hi/lo
__device__ __half g_h[(size_t)NP*NT*NF];                                  // A for mm2 (fp16)

// ---------------- PTX helpers (arch-neutral, sm_80-era) ----------------
__device__ __forceinline__ uint32_t s2u(const void* p) {
    uint32_t a;
    asm("{ .reg .u64 t; cvta.to.shared.u64 t, %1; cvt.u32.u64 %0, t; }" : "=r"(a) : "l"(p));
    return a;
}
__device__ __forceinline__ void cp16(uint32_t dst, const void* src) {
    asm volatile("cp.async.cg.shared.global [%0], [%1], 16;" :: "r"(dst), "l"(src));
}
#define CP_COMMIT() asm volatile("cp.async.commit_group;" ::: "memory")
#define CP_WAIT(n)  asm volatile("cp.async.wait_group %0;" :: "n"(n) : "memory")

__device__ __forceinline__ void ldm4(uint32_t* r, uint32_t a) {
    asm volatile("ldmatrix.sync.aligned.m8n8.x4.shared.b16 {%0,%1,%2,%3}, [%4];"
        : "=r"(r[0]), "=r"(r[1]), "=r"(r[2]), "=r"(r[3]) : "r"(a));
}
__device__ __forceinline__ void ldm4t(uint32_t* r, uint32_t a) {
    asm volatile("ldmatrix.sync.aligned.m8n8.x4.trans.shared.b16 {%0,%1,%2,%3}, [%4];"
        : "=r"(r[0]), "=r"(r[1]), "=r"(r[2]), "=r"(r[3]) : "r"(a));
}
__device__ __forceinline__ void mma(float* d, const uint32_t* a, uint32_t b0, uint32_t b1) {
    asm volatile("mma.sync.aligned.m16n8k16.row.col.f32.f16.f16.f32 "
        "{%0,%1,%2,%3}, {%4,%5,%6,%7}, {%8,%9}, {%0,%1,%2,%3};"
        : "+f"(d[0]), "+f"(d[1]), "+f"(d[2]), "+f"(d[3])
        : "r"(a[0]), "r"(a[1]), "r"(a[2]), "r"(a[3]), "r"(b0), "r"(b1));
}
__device__ __forceinline__ uint32_t pack_h2(float a, float b) {
    __half2 t = __floats2half2_rn(a, b);
    return *(uint32_t*)&t;
}

// ---------------- prepass kernels ----------------
__global__ void k_pool(const float* __restrict__ x) {
    int b = blockIdx.y, ch = blockIdx.z;
    int d = blockIdx.x * 256 + threadIdx.x;
    const float* xp = x + ((size_t)b * NT + ch * 128) * ND + d;
    float s = 0.f;
#pragma unroll 8
    for (int t = 0; t < 128; ++t) s += xp[(size_t)t * ND];
    g_ppart[(b * ND + d) * 16 + ch] = s;
}

constexpr int N_X4 = NB * NT * ND / 4;
constexpr int N_W4 = NE * ND * NF / 4;
__global__ void k_cvt_all(const float4* __restrict__ x,
                          const float4* __restrict__ W1,
                          const float4* __restrict__ W2) {
    int gid = blockIdx.x * 256 + threadIdx.x;
    if (gid < N_X4) {                       // x -> single fp16
        float4 v = x[gid];
        uint32_t* H = (uint32_t*)g_x;
        H[2*gid]   = pack_h2(v.x, v.y);
        H[2*gid+1] = pack_h2(v.z, v.w);
        return;
    }
    const float4* src;  uint32_t *H, *L;  int i;
    if (gid < N_X4 + N_W4) {
        src = W1; i = gid - N_X4;
        H = (uint32_t*)g_w1h; L = (uint32_t*)g_w1l;
    } else {
        src = W2; i = gid - N_X4 - N_W4;
        H = (uint32_t*)g_w2h; L = (uint32_t*)g_w2l;
    }
    float4 v = src[i];
    float h0 = __half2float(__float2half_rn(v.x));
    float h1 = __half2float(__float2half_rn(v.y));
    float h2 = __half2float(__float2half_rn(v.z));
    float h3 = __half2float(__float2half_rn(v.w));
    H[2*i]   = pack_h2(v.x, v.y);
    H[2*i+1] = pack_h2(v.z, v.w);
    L[2*i]   = pack_h2(v.x - h0, v.y - h1);
    L[2*i+1] = pack_h2(v.z - h2, v.w - h3);
}

__global__ void k_route(const float* __restrict__ Wr) {
    __shared__ float pooled[NB * ND];
    __shared__ float lg[NB][NE];
    int t = threadIdx.x;   // 64 threads
    for (int i = t; i < NB * ND; i += 64) {
        float s = 0.f;
#pragma unroll
        for (int ch = 0; ch < 16; ++ch) s += g_ppart[i * 16 + ch];
        pooled[i] = s * (1.0f / NT);
    }
    __syncthreads();
    if (t < NB * NE) {
        int b = t / NE, e = t % NE;
        float s = 0.f;
        for (int d = 0; d < ND; ++d) s += pooled[b * ND + d] * Wr[d * NE + e];
        lg[b][e] = s;
    }
    __syncthreads();
    if (t < NB) {
        int b = t;
        int i0 = 0; float v0 = lg[b][0];
#pragma unroll
        for (int e = 1; e < NE; ++e) if (lg[b][e] > v0) { v0 = lg[b][e]; i0 = e; }
        int i1 = (i0 == 0) ? 1 : 0; float v1 = lg[b][i1];
#pragma unroll
        for (int e = 0; e < NE; ++e) if (e != i0 && lg[b][e] > v1) { v1 = lg[b][e]; i1 = e; }
        float e1 = expf(v1 - v0);
        float inv = 1.f / (1.f + e1);
        g_eidx[2 * b] = i0;  g_eidx[2 * b + 1] = i1;
        g_wgt[2 * b] = inv;  g_wgt[2 * b + 1] = e1 * inv;
    }
}

// ---------------- GEMM mainloop pieces ----------------
// Stage: A [128 x 32] fp16, B [32 x 128] hi+lo fp16; 6 cp.async per thread.
__device__ __forceinline__ void load_stage(uint32_t smb, int buf, int tid,
    const __half* __restrict__ A, int lda,
    const __half* __restrict__ Bh, const __half* __restrict__ Bl, int ldb, int k0)
{
    uint32_t base = smb + buf * BUF;
#pragma unroll
    for (int i = 0; i < 2; ++i) {      // A: 512 16B chunks
        int c = tid + i * 256;
        int row = c >> 2, kc = c & 3;
        size_t go = (size_t)row * lda + k0 + kc * 8;
        cp16(base + row * A_STRIDE_B + kc * 16, A + go);
    }
#pragma unroll
    for (int i = 0; i < 2; ++i) {      // B: 512 16B chunks per tile, hi+lo
        int c = tid + i * 256;
        int row = c >> 4, nc = c & 15;
        size_t go = (size_t)(k0 + row) * ldb + nc * 8;
        uint32_t d = base + BOFF + row * B_STRIDE_B + nc * 16;
        cp16(d, Bh + go);
        cp16(d + B_TILE, Bl + go);
    }
}

// Warp tile 64M x 32N, 2 passes (A*Bh, A*Bl).
__device__ __forceinline__ void compute_stage(uint32_t smb, int buf, int lane,
                                              int warpM, int warpN, float acc[4][4][4])
{
    uint32_t base = smb + buf * BUF;
    int lr = lane & 15, lc = lane >> 4;
#pragma unroll
    for (int ks = 0; ks < 2; ++ks) {
        uint32_t bh[2][4], bl[2][4];
#pragma unroll
        for (int nt = 0; nt < 2; ++nt) {
            uint32_t bd = base + BOFF + (ks * 16 + lr) * B_STRIDE_B + (warpN * 32 + nt * 16 + lc * 8) * 2;
            ldm4t(bh[nt], bd);
            ldm4t(bl[nt], bd + B_TILE);
        }
#pragma unroll
        for (int mt = 0; mt < 4; ++mt) {
            uint32_t a[4];
            uint32_t ad = base + (warpM * 64 + mt * 16 + lr) * A_STRIDE_B + (ks * 16 + lc * 8) * 2;
            ldm4(a, ad);
#pragma unroll
            for (int nt = 0; nt < 2; ++nt)
#pragma unroll
                for (int n8 = 0; n8 < 2; ++n8) {
                    float* d = acc[mt][nt * 2 + n8];
                    mma(d, a, bh[nt][2 * n8], bh[nt][2 * n8 + 1]);   // A * W_hi
                    mma(d, a, bl[nt][2 * n8], bl[nt][2 * n8 + 1]);   // A * W_lo
                }
        }
    }
}

// ---------------- GEMM1: h[p] = w * gelu(x[b] @ W1[e] + b1[e]) --------------
__global__ __launch_bounds__(THREADS, 2)
void k_mm1(const float* __restrict__ b1) {
    extern __shared__ char sm[];
    const uint32_t smb = s2u(sm);
    const int tid = threadIdx.x, lane = tid & 31, w = tid >> 5;
    const int warpM = w >> 2, warpN = w & 3;
    const int p = blockIdx.z, b = p >> 1;
    const int e = g_eidx[p];
    const float wsc = g_wgt[p];
    const int m0 = blockIdx.y * BM, n0 = blockIdx.x * BN;

    const __half* A  = g_x   + ((size_t)b * NT + m0) * ND;
    const __half* Bh = g_w1h + (size_t)e * ND * NF + n0;
    const __half* Bl = g_w1l + (size_t)e * ND * NF + n0;

    float acc[4][4][4];
#pragma unroll
    for (int i = 0; i < 4; ++i)
#pragma unroll
        for (int j = 0; j < 4; ++j)
#pragma unroll
            for (int q = 0; q < 4; ++q) acc[i][j][q] = 0.f;

    constexpr int KT = ND / BK;   // 32
    load_stage(smb, 0, tid, A, ND, Bh, Bl, NF, 0);   CP_COMMIT();
    load_stage(smb, 1, tid, A, ND, Bh, Bl, NF, BK);  CP_COMMIT();

    int buf = 0, nbuf = 2;
    for (int s = 0; s < KT; ++s) {
        if (s + 1 < KT) CP_WAIT(1); else CP_WAIT(0);
        __syncthreads();
        if (s + 2 < KT) {
            load_stage(smb, nbuf, tid, A, ND, Bh, Bl, NF, (s + 2) * BK);
            CP_COMMIT();
        }
        compute_stage(smb, buf, lane, warpM, warpN, acc);
        buf = (buf == NSTAGE - 1) ? 0 : buf + 1;
        nbuf = (nbuf == NSTAGE - 1) ? 0 : nbuf + 1;
    }

    // epilogue: bias + exact erf-gelu + router weight, store h as fp16
    const float* bg = b1 + (size_t)e * NF;
#pragma unroll
    for (int mt = 0; mt < 4; ++mt)
#pragma unroll
        for (int nn = 0; nn < 4; ++nn) {
            int row = m0 + warpM * 64 + mt * 16 + (lane >> 2);
            int col = n0 + warpN * 32 + nn * 8 + (lane & 3) * 2;
            float bv0 = bg[col], bv1 = bg[col + 1];
            float v00 = acc[mt][nn][0] + bv0, v01 = acc[mt][nn][1] + bv1;
            float v10 = acc[mt][nn][2] + bv0, v11 = acc[mt][nn][3] + bv1;
            float g00 = wsc * v00 * normcdff(v00);
            float g01 = wsc * v01 * normcdff(v01);
            float g10 = wsc * v10 * normcdff(v10);
            float g11 = wsc * v11 * normcdff(v11);
            size_t o0 = ((size_t)p * NT + row) * NF + col;
            size_t o1 = ((size_t)p * NT + row + 8) * NF + col;
            *(uint32_t*)&g_h[o0] = pack_h2(g00, g01);
            *(uint32_t*)&g_h[o1] = pack_h2(g10, g11);
        }
}

// ---------------- GEMM2: out[b] = sum_k h[b,k] @ W2[e_k] + weighted bias ----
__global__ __launch_bounds__(THREADS, 2)
void k_mm2(const float* __restrict__ b2, float* __restrict__ out) {
    extern __shared__ char sm[];
    const uint32_t smb = s2u(sm);
    const int tid = threadIdx.x, lane = tid & 31, w = tid >> 5;
    const int warpM = w >> 2, warpN = w & 3;
    const int b = blockIdx.z;
    const int e0 = g_eidx[2 * b], e1 = g_eidx[2 * b + 1];
    const float w0 = g_wgt[2 * b], w1 = g_wgt[2 * b + 1];
    const int m0 = blockIdx.y * BM, n0 = blockIdx.x * BN;

    float acc[4][4][4];
#pragma unroll
    for (int i = 0; i < 4; ++i)
#pragma unroll
        for (int j = 0; j < 4; ++j)
#pragma unroll
            for (int q = 0; q < 4; ++q) acc[i][j][q] = 0.f;

    constexpr int KSEG = NF / BK;      // 128 stages per expert
    constexpr int KT   = 2 * KSEG;     // 256

    auto stage_ptrs = [&](int s, const __half*& A, const __half*& Bh,
                          const __half*& Bl, int& k0) {
        int seg = s >> 7, sl = s & (KSEG - 1);
        int p = 2 * b + seg, e = seg ? e1 : e0;
        A  = g_h   + ((size_t)p * NT + m0) * NF;
        Bh = g_w2h + (size_t)e * NF * ND + n0;
        Bl = g_w2l + (size_t)e * NF * ND + n0;
        k0 = sl * BK;
    };

    {
        const __half *A, *Bh, *Bl; int k0;
        stage_ptrs(0, A, Bh, Bl, k0);
        load_stage(smb, 0, tid, A, NF, Bh, Bl, ND, k0);  CP_COMMIT();
        stage_ptrs(1, A, Bh, Bl, k0);
        load_stage(smb, 1, tid, A, NF, Bh, Bl, ND, k0);  CP_COMMIT();
    }

    int buf = 0, nbuf = 2;
    for (int s = 0; s < KT; ++s) {
        if (s + 1 < KT) CP_WAIT(1); else CP_WAIT(0);
        __syncthreads();
        if (s + 2 < KT) {
            const __half *A, *Bh, *Bl; int k0;
            stage_ptrs(s + 2, A, Bh, Bl, k0);
            load_stage(smb, nbuf, tid, A, NF, Bh, Bl, ND, k0);
            CP_COMMIT();
        }
        compute_stage(smb, buf, lane, warpM, warpN, acc);
        buf = (buf == NSTAGE - 1) ? 0 : buf + 1;
        nbuf = (nbuf == NSTAGE - 1) ? 0 : nbuf + 1;
    }

    // epilogue: weighted bias, final fp32 output
#pragma unroll
    for (int mt = 0; mt < 4; ++mt)
#pragma unroll
        for (int nn = 0; nn < 4; ++nn) {
            int row = m0 + warpM * 64 + mt * 16 + (lane >> 2);
            int col = n0 + warpN * 32 + nn * 8 + (lane & 3) * 2;
            float bv0 = w0 * b2[e0 * ND + col]     + w1 * b2[e1 * ND + col];
            float bv1 = w0 * b2[e0 * ND + col + 1] + w1 * b2[e1 * ND + col + 1];
            float* o0 = out + ((size_t)b * NT + row) * ND + col;
            float* o1 = out + ((size_t)b * NT + row + 8) * ND + col;
            o0[0] = acc[mt][nn][0] + bv0;  o0[1] = acc[mt][nn][1] + bv1;
            o1[0] = acc[mt][nn][2] + bv0;  o1[1] = acc[mt][nn][3] + bv1;
        }
}

// ---------------- launch (k_mm1 at position 4 for ncu) ----------------------
extern "C" void kernel_launch(void* const* d_in, const int* in_sizes, int n_in,
                              void* d_out, int out_size) {
    const float* x  = (const float*)d_in[0];
    const float* Wr = (const float*)d_in[1];
    const float* W1 = (const float*)d_in[2];
    const float* b1 = (const float*)d_in[3];
    const float* W2 = (const float*)d_in[4];
    const float* b2 = (const float*)d_in[5];
    float* out = (float*)d_out;

    cudaFuncSetAttribute(k_mm1, cudaFuncAttributeMaxDynamicSharedMemorySize, SMEM_TOTAL);
    cudaFuncSetAttribute(k_mm2, cudaFuncAttributeMaxDynamicSharedMemorySize, SMEM_TOTAL);

    k_pool<<<dim3(ND / 256, NB, 16), 256>>>(x);                             // 1
    k_route<<<1, 64>>>(Wr);                                                  // 2
    k_cvt_all<<<(N_X4 + 2 * N_W4 + 255) / 256, 256>>>(
        (const float4*)x, (const float4*)W1, (const float4*)W2);             // 3
    k_mm1<<<dim3(NF/BN, NT/BM, NP), THREADS, SMEM_TOTAL>>>(b1);              // 4 <- ncu
    k_mm2<<<dim3(ND/BN, NT/BM, NB), THREADS, SMEM_TOTAL>>>(b2, out);         // 5
}

// round 10
// speedup vs baseline: 2.5624x; 1.6917x over previous
#include <cuda_runtime.h>
#include <cuda_fp16.h>
#include <cstdint>

// ---------------- problem constants ----------------
constexpr int NB = 8, NT = 2048, ND = 1024, NF = 4096, NE = 8, NP = 16;
constexpr int BM = 128, BN = 128, BK = 64;
constexpr int THREADS = 256;

// smem layout (bytes): A row = 64*2+16 = 144B, B row = 128*2+16 = 272B
constexpr int A_STRIDE_B = 144;
constexpr int B_STRIDE_B = 272;
constexpr int A_TILE = BM * A_STRIDE_B;            // 18432
constexpr int B_TILE = BK * B_STRIDE_B;            // 17408
constexpr int BOFF   = A_TILE;                     // 18432
constexpr int BUF    = A_TILE + B_TILE;            // 35840
constexpr int NSTAGE = 3;
constexpr int SMEM_TOTAL = NSTAGE * BUF;           // 107520 (x2 CTAs = 215040 < 228KB)

// ---------------- device scratch (allocation-free) ----------------
__device__ float g_ppart[NB * ND * 16];
__device__ int   g_eidx[NP];
__device__ float g_wgt[NP];
__device__ __half g_x[(size_t)NB*NT*ND];             // fp16 x
__device__ __half g_w1[(size_t)NE*ND*NF];            // fp16 W1
__device__ __half g_w2[(size_t)NE*NF*ND];            // fp16 W2
__device__ __half g_h[(size_t)NP*NT*NF];             // fp16 h

// ---------------- PTX helpers (arch-neutral, sm_80-era) ----------------
__device__ __forceinline__ uint32_t s2u(const void* p) {
    uint32_t a;
    asm("{ .reg .u64 t; cvta.to.shared.u64 t, %1; cvt.u32.u64 %0, t; }" : "=r"(a) : "l"(p));
    return a;
}
__device__ __forceinline__ void cp16(uint32_t dst, const void* src) {
    asm volatile("cp.async.cg.shared.global [%0], [%1], 16;" :: "r"(dst), "l"(src));
}
#define CP_COMMIT() asm volatile("cp.async.commit_group;" ::: "memory")
#define CP_WAIT(n)  asm volatile("cp.async.wait_group %0;" :: "n"(n) : "memory")

__device__ __forceinline__ void ldm4(uint32_t* r, uint32_t a) {
    asm volatile("ldmatrix.sync.aligned.m8n8.x4.shared.b16 {%0,%1,%2,%3}, [%4];"
        : "=r"(r[0]), "=r"(r[1]), "=r"(r[2]), "=r"(r[3]) : "r"(a));
}
__device__ __forceinline__ void ldm4t(uint32_t* r, uint32_t a) {
    asm volatile("ldmatrix.sync.aligned.m8n8.x4.trans.shared.b16 {%0,%1,%2,%3}, [%4];"
        : "=r"(r[0]), "=r"(r[1]), "=r"(r[2]), "=r"(r[3]) : "r"(a));
}
__device__ __forceinline__ void mma(float* d, const uint32_t* a, uint32_t b0, uint32_t b1) {
    asm volatile("mma.sync.aligned.m16n8k16.row.col.f32.f16.f16.f32 "
        "{%0,%1,%2,%3}, {%4,%5,%6,%7}, {%8,%9}, {%0,%1,%2,%3};"
        : "+f"(d[0]), "+f"(d[1]), "+f"(d[2]), "+f"(d[3])
        : "r"(a[0]), "r"(a[1]), "r"(a[2]), "r"(a[3]), "r"(b0), "r"(b1));
}
__device__ __forceinline__ uint32_t pack_h2(float a, float b) {
    __half2 t = __floats2half2_rn(a, b);
    return *(uint32_t*)&t;
}

// ---------------- prepass kernels ----------------
__global__ void k_pool(const float* __restrict__ x) {
    int b = blockIdx.y, ch = blockIdx.z;
    int d = blockIdx.x * 256 + threadIdx.x;
    const float* xp = x + ((size_t)b * NT + ch * 128) * ND + d;
    float s = 0.f;
#pragma unroll 8
    for (int t = 0; t < 128; ++t) s += xp[(size_t)t * ND];
    g_ppart[(b * ND + d) * 16 + ch] = s;
}

constexpr int N_X4 = NB * NT * ND / 4;
constexpr int N_W4 = NE * ND * NF / 4;
__global__ void k_cvt_all(const float4* __restrict__ x,
                          const float4* __restrict__ W1,
                          const float4* __restrict__ W2) {
    int gid = blockIdx.x * 256 + threadIdx.x;
    const float4* src;  uint32_t* H;  int i;
    if (gid < N_X4) {
        src = x; i = gid;  H = (uint32_t*)g_x;
    } else if (gid < N_X4 + N_W4) {
        src = W1; i = gid - N_X4;  H = (uint32_t*)g_w1;
    } else {
        src = W2; i = gid - N_X4 - N_W4;  H = (uint32_t*)g_w2;
    }
    float4 v = src[i];
    H[2*i]   = pack_h2(v.x, v.y);
    H[2*i+1] = pack_h2(v.z, v.w);
}

__global__ void k_route(const float* __restrict__ Wr) {
    __shared__ float pooled[NB * ND];
    __shared__ float lg[NB][NE];
    int t = threadIdx.x;   // 64 threads
    for (int i = t; i < NB * ND; i += 64) {
        float s = 0.f;
#pragma unroll
        for (int ch = 0; ch < 16; ++ch) s += g_ppart[i * 16 + ch];
        pooled[i] = s * (1.0f / NT);
    }
    __syncthreads();
    if (t < NB * NE) {
        int b = t / NE, e = t % NE;
        float s = 0.f;
        for (int d = 0; d < ND; ++d) s += pooled[b * ND + d] * Wr[d * NE + e];
        lg[b][e] = s;
    }
    __syncthreads();
    if (t < NB) {
        int b = t;
        int i0 = 0; float v0 = lg[b][0];
#pragma unroll
        for (int e = 1; e < NE; ++e) if (lg[b][e] > v0) { v0 = lg[b][e]; i0 = e; }
        int i1 = (i0 == 0) ? 1 : 0; float v1 = lg[b][i1];
#pragma unroll
        for (int e = 0; e < NE; ++e) if (e != i0 && lg[b][e] > v1) { v1 = lg[b][e]; i1 = e; }
        float e1 = expf(v1 - v0);
        float inv = 1.f / (1.f + e1);
        g_eidx[2 * b] = i0;  g_eidx[2 * b + 1] = i1;
        g_wgt[2 * b] = inv;  g_wgt[2 * b + 1] = e1 * inv;
    }
}

// ---------------- GEMM mainloop pieces ----------------
// Stage: A [128 x 64] fp16, B [64 x 128] fp16; 8 cp.async per thread.
__device__ __forceinline__ void load_stage(uint32_t smb, int buf, int tid,
    const __half* __restrict__ A, int lda,
    const __half* __restrict__ B, int ldb, int k0)
{
    uint32_t base = smb + buf * BUF;
#pragma unroll
    for (int i = 0; i < 4; ++i) {      // A: 1024 16B chunks (128 rows x 8)
        int c = tid + i * 256;
        int row = c >> 3, kc = c & 7;
        size_t go = (size_t)row * lda + k0 + kc * 8;
        cp16(base + row * A_STRIDE_B + kc * 16, A + go);
    }
#pragma unroll
    for (int i = 0; i < 4; ++i) {      // B: 1024 16B chunks (64 rows x 16)
        int c = tid + i * 256;
        int row = c >> 4, nc = c & 15;
        size_t go = (size_t)(k0 + row) * ldb + nc * 8;
        cp16(base + BOFF + row * B_STRIDE_B + nc * 16, B + go);
    }
}

// Warp tile 64M x 32N, single fp16 pass; 4 K16 sub-steps per stage.
__device__ __forceinline__ void compute_stage(uint32_t smb, int buf, int lane,
                                              int warpM, int warpN, float acc[4][4][4])
{
    uint32_t base = smb + buf * BUF;
    int lr = lane & 15, lc = lane >> 4;
#pragma unroll
    for (int ks = 0; ks < 4; ++ks) {
        uint32_t bf[2][4];
#pragma unroll
        for (int nt = 0; nt < 2; ++nt) {
            uint32_t bd = base + BOFF + (ks * 16 + lr) * B_STRIDE_B + (warpN * 32 + nt * 16 + lc * 8) * 2;
            ldm4t(bf[nt], bd);
        }
#pragma unroll
        for (int mt = 0; mt < 4; ++mt) {
            uint32_t a[4];
            uint32_t ad = base + (warpM * 64 + mt * 16 + lr) * A_STRIDE_B + (ks * 16 + lc * 8) * 2;
            ldm4(a, ad);
#pragma unroll
            for (int nt = 0; nt < 2; ++nt)
#pragma unroll
                for (int n8 = 0; n8 < 2; ++n8)
                    mma(acc[mt][nt * 2 + n8], a, bf[nt][2 * n8], bf[nt][2 * n8 + 1]);
        }
    }
}

// ---------------- GEMM1: h[p] = w * gelu(x[b] @ W1[e] + b1[e]) --------------
__global__ __launch_bounds__(THREADS, 2)
void k_mm1(const float* __restrict__ b1) {
    extern __shared__ char sm[];
    const uint32_t smb = s2u(sm);
    const int tid = threadIdx.x, lane = tid & 31, w = tid >> 5;
    const int warpM = w >> 2, warpN = w & 3;
    const int p = blockIdx.z, b = p >> 1;
    const int e = g_eidx[p];
    const float wsc = g_wgt[p];
    const int m0 = blockIdx.y * BM, n0 = blockIdx.x * BN;

    const __half* A = g_x  + ((size_t)b * NT + m0) * ND;
    const __half* B = g_w1 + (size_t)e * ND * NF + n0;

    float acc[4][4][4];
#pragma unroll
    for (int i = 0; i < 4; ++i)
#pragma unroll
        for (int j = 0; j < 4; ++j)
#pragma unroll
            for (int q = 0; q < 4; ++q) acc[i][j][q] = 0.f;

    constexpr int KT = ND / BK;   // 16
    load_stage(smb, 0, tid, A, ND, B, NF, 0);   CP_COMMIT();
    load_stage(smb, 1, tid, A, ND, B, NF, BK);  CP_COMMIT();

    int buf = 0, nbuf = 2;
    for (int s = 0; s < KT; ++s) {
        if (s + 1 < KT) CP_WAIT(1); else CP_WAIT(0);
        __syncthreads();
        if (s + 2 < KT) {
            load_stage(smb, nbuf, tid, A, ND, B, NF, (s + 2) * BK);
            CP_COMMIT();
        }
        compute_stage(smb, buf, lane, warpM, warpN, acc);
        buf = (buf == NSTAGE - 1) ? 0 : buf + 1;
        nbuf = (nbuf == NSTAGE - 1) ? 0 : nbuf + 1;
    }

    // epilogue: bias + exact erf-gelu + router weight, store h as fp16
    const float* bg = b1 + (size_t)e * NF;
#pragma unroll
    for (int mt = 0; mt < 4; ++mt)
#pragma unroll
        for (int nn = 0; nn < 4; ++nn) {
            int row = m0 + warpM * 64 + mt * 16 + (lane >> 2);
            int col = n0 + warpN * 32 + nn * 8 + (lane & 3) * 2;
            float bv0 = bg[col], bv1 = bg[col + 1];
            float v00 = acc[mt][nn][0] + bv0, v01 = acc[mt][nn][1] + bv1;
            float v10 = acc[mt][nn][2] + bv0, v11 = acc[mt][nn][3] + bv1;
            float g00 = wsc * v00 * normcdff(v00);
            float g01 = wsc * v01 * normcdff(v01);
            float g10 = wsc * v10 * normcdff(v10);
            float g11 = wsc * v11 * normcdff(v11);
            size_t o0 = ((size_t)p * NT + row) * NF + col;
            size_t o1 = ((size_t)p * NT + row + 8) * NF + col;
            *(uint32_t*)&g_h[o0] = pack_h2(g00, g01);
            *(uint32_t*)&g_h[o1] = pack_h2(g10, g11);
        }
}

// ---------------- GEMM2: out[b] = sum_k h[b,k] @ W2[e_k] + weighted bias ----
__global__ __launch_bounds__(THREADS, 2)
void k_mm2(const float* __restrict__ b2, float* __restrict__ out) {
    extern __shared__ char sm[];
    const uint32_t smb = s2u(sm);
    const int tid = threadIdx.x, lane = tid & 31, w = tid >> 5;
    const int warpM = w >> 2, warpN = w & 3;
    const int b = blockIdx.z;
    const int e0 = g_eidx[2 * b], e1 = g_eidx[2 * b + 1];
    const float w0 = g_wgt[2 * b], w1 = g_wgt[2 * b + 1];
    const int m0 = blockIdx.y * BM, n0 = blockIdx.x * BN;

    float acc[4][4][4];
#pragma unroll
    for (int i = 0; i < 4; ++i)
#pragma unroll
        for (int j = 0; j < 4; ++j)
#pragma unroll
            for (int q = 0; q < 4; ++q) acc[i][j][q] = 0.f;

    constexpr int KSEG = NF / BK;      // 64 stages per expert
    constexpr int KT   = 2 * KSEG;     // 128

    auto stage_ptrs = [&](int s, const __half*& A, const __half*& B, int& k0) {
        int seg = s >> 6, sl = s & (KSEG - 1);
        int p = 2 * b + seg, e = seg ? e1 : e0;
        A = g_h  + ((size_t)p * NT + m0) * NF;
        B = g_w2 + (size_t)e * NF * ND + n0;
        k0 = sl * BK;
    };

    {
        const __half *A, *B; int k0;
        stage_ptrs(0, A, B, k0);
        load_stage(smb, 0, tid, A, NF, B, ND, k0);  CP_COMMIT();
        stage_ptrs(1, A, B, k0);
        load_stage(smb, 1, tid, A, NF, B, ND, k0);  CP_COMMIT();
    }

    int buf = 0, nbuf = 2;
    for (int s = 0; s < KT; ++s) {
        if (s + 1 < KT) CP_WAIT(1); else CP_WAIT(0);
        __syncthreads();
        if (s + 2 < KT) {
            const __half *A, *B; int k0;
            stage_ptrs(s + 2, A, B, k0);
            load_stage(smb, nbuf, tid, A, NF, B, ND, k0);
            CP_COMMIT();
        }
        compute_stage(smb, buf, lane, warpM, warpN, acc);
        buf = (buf == NSTAGE - 1) ? 0 : buf + 1;
        nbuf = (nbuf == NSTAGE - 1) ? 0 : nbuf + 1;
    }

    // epilogue: weighted bias, final fp32 output
#pragma unroll
    for (int mt = 0; mt < 4; ++mt)
#pragma unroll
        for (int nn = 0; nn < 4; ++nn) {
            int row = m0 + warpM * 64 + mt * 16 + (lane >> 2);
            int col = n0 + warpN * 32 + nn * 8 + (lane & 3) * 2;
            float bv0 = w0 * b2[e0 * ND + col]     + w1 * b2[e1 * ND + col];
            float bv1 = w0 * b2[e0 * ND + col + 1] + w1 * b2[e1 * ND + col + 1];
            float* o0 = out + ((size_t)b * NT + row) * ND + col;
            float* o1 = out + ((size_t)b * NT + row + 8) * ND + col;
            o0[0] = acc[mt][nn][0] + bv0;  o0[1] = acc[mt][nn][1] + bv1;
            o1[0] = acc[mt][nn][2] + bv0;  o1[1] = acc[mt][nn][3] + bv1;
        }
}

// ---------------- launch (k_mm1 at position 4 for ncu) ----------------------
extern "C" void kernel_launch(void* const* d_in, const int* in_sizes, int n_in,
                              void* d_out, int out_size) {
    const float* x  = (const float*)d_in[0];
    const float* Wr = (const float*)d_in[1];
    const float* W1 = (const float*)d_in[2];
    const float* b1 = (const float*)d_in[3];
    const float* W2 = (const float*)d_in[4];
    const float* b2 = (const float*)d_in[5];
    float* out = (float*)d_out;

    cudaFuncSetAttribute(k_mm1, cudaFuncAttributeMaxDynamicSharedMemorySize, SMEM_TOTAL);
    cudaFuncSetAttribute(k_mm2, cudaFuncAttributeMaxDynamicSharedMemorySize, SMEM_TOTAL);

    k_pool<<<dim3(ND / 256, NB, 16), 256>>>(x);                             // 1
    k_route<<<1, 64>>>(Wr);                                                  // 2
    k_cvt_all<<<(N_X4 + 2 * N_W4 + 255) / 256, 256>>>(
        (const float4*)x, (const float4*)W1, (const float4*)W2);             // 3
    k_mm1<<<dim3(NF/BN, NT/BM, NP), THREADS, SMEM_TOTAL>>>(b1);              // 4 <- ncu
    k_mm2<<<dim3(ND/BN, NT/BM, NB), THREADS, SMEM_TOTAL>>>(b2, out);         // 5
}